// round 1
// baseline (speedup 1.0000x reference)
#include <cuda_runtime.h>
#include <cuda_bf16.h>
#include <stdint.h>

// Problem constants (fixed by the reference)
#define B_   64
#define N_   2048
#define D_   512
#define K_   64
#define KG_  80                      // K + ghost clusters
#define ROWS_TOTAL (B_ * N_)         // 131072

// ---------------- scratch (__device__ globals: allocation-free) -------------
__device__ float          g_a[(size_t)ROWS_TOTAL * KG_];      // 41.9 MB  a = x@clusters
__device__ float          g_colsum[KG_];
__device__ float          g_colsumsq[KG_];
__device__ __nv_bfloat16  g_at_hi[(size_t)B_ * K_ * N_];      // 16 MB  assignment^T hi
__device__ __nv_bfloat16  g_at_lo[(size_t)B_ * K_ * N_];      // 16 MB  assignment^T lo
__device__ float          g_asum[B_ * K_];
__device__ float          g_vraw[(size_t)B_ * K_ * D_];       // 8 MB   vlad (B,K,D) pre-norm

// ---------------- helpers ---------------------------------------------------
__device__ __forceinline__ void mma16816(float* c, const uint32_t* a, const uint32_t* b) {
    asm volatile(
        "mma.sync.aligned.m16n8k16.row.col.f32.bf16.bf16.f32 "
        "{%0,%1,%2,%3}, {%4,%5,%6,%7}, {%8,%9}, {%0,%1,%2,%3};\n"
        : "+f"(c[0]), "+f"(c[1]), "+f"(c[2]), "+f"(c[3])
        : "r"(a[0]), "r"(a[1]), "r"(a[2]), "r"(a[3]), "r"(b[0]), "r"(b[1]));
}

__device__ __forceinline__ void split_bf16(float v, __nv_bfloat16& h, __nv_bfloat16& l) {
    h = __float2bfloat16(v);
    l = __float2bfloat16(v - __bfloat162float(h));
}

// ---------------- K0: zero the atomically-accumulated scratch ---------------
__global__ void k0_zero() {
    int t = blockIdx.x * blockDim.x + threadIdx.x;
    if (t < KG_) { g_colsum[t] = 0.0f; g_colsumsq[t] = 0.0f; }
    if (t < B_ * K_) g_asum[t] = 0.0f;
}

// ---------------- K1: a = x @ clusters (131072x512 @ 512x80), bf16x3 --------
// block tile M=128, Ntile=80 (full), K-chunk 32. 256 thr = 4 Mwarps x 2 Nwarps.
#define SA_STRIDE 56   // 32 data + pad; conflict-free ldfrag, rows 16B-multiple
#define SB_STRIDE 40
__global__ __launch_bounds__(256, 2)
void k1_gemm1(const float* __restrict__ x, const float* __restrict__ clusters) {
    __shared__ __nv_bfloat16 sA[2][128 * SA_STRIDE];   // x chunk  [row][k]   hi/lo
    __shared__ __nv_bfloat16 sB[2][KG_ * SB_STRIDE];   // clusters chunk transposed [n][k]
    const int tid = threadIdx.x, warp = tid >> 5, lane = tid & 31;
    const int row0 = blockIdx.x * 128;
    const float* xblk = x + (size_t)row0 * D_;

    const int mrow = (warp & 3) * 32;        // warp's 32 rows
    const int ncol = (warp >> 2) * 40;       // warp's 40 cols (5 x n8)

    float acc[2][5][4];
#pragma unroll
    for (int m = 0; m < 2; m++)
#pragma unroll
        for (int n = 0; n < 5; n++)
#pragma unroll
            for (int j = 0; j < 4; j++) acc[m][n][j] = 0.0f;

    for (int kc = 0; kc < D_; kc += 32) {
        // load x chunk 128x32 fp32, split into hi/lo
#pragma unroll
        for (int p = 0; p < 4; p++) {
            int r  = p * 32 + (tid >> 3);
            int c4 = (tid & 7) * 4;
            float4 v = *(const float4*)(xblk + (size_t)r * D_ + kc + c4);
            __nv_bfloat16 h, l;
            float vv[4] = {v.x, v.y, v.z, v.w};
#pragma unroll
            for (int j = 0; j < 4; j++) {
                split_bf16(vv[j], h, l);
                sA[0][r * SA_STRIDE + c4 + j] = h;
                sA[1][r * SA_STRIDE + c4 + j] = l;
            }
        }
        // load clusters chunk 32x80, store transposed [n][k]
#pragma unroll
        for (int p = 0; p < 10; p++) {
            int idx = p * 256 + tid;               // < 2560
            int kr = idx / KG_, n = idx % KG_;
            float v = clusters[(size_t)(kc + kr) * KG_ + n];
            __nv_bfloat16 h, l;
            split_bf16(v, h, l);
            sB[0][n * SB_STRIDE + kr] = h;
            sB[1][n * SB_STRIDE + kr] = l;
        }
        __syncthreads();

#pragma unroll
        for (int ks = 0; ks < 2; ks++) {
            const int kb = ks * 16;
            const int kk = kb + (lane & 3) * 2;
            uint32_t bf[5][2][2];
#pragma unroll
            for (int n = 0; n < 5; n++) {
                int nc = ncol + n * 8 + (lane >> 2);
#pragma unroll
                for (int s = 0; s < 2; s++) {
                    bf[n][s][0] = *(const uint32_t*)(&sB[s][nc * SB_STRIDE + kk]);
                    bf[n][s][1] = *(const uint32_t*)(&sB[s][nc * SB_STRIDE + kk + 8]);
                }
            }
#pragma unroll
            for (int m = 0; m < 2; m++) {
                int r = mrow + m * 16 + (lane >> 2);
                uint32_t ah[4], al[4];
                ah[0] = *(const uint32_t*)(&sA[0][r * SA_STRIDE + kk]);
                ah[1] = *(const uint32_t*)(&sA[0][(r + 8) * SA_STRIDE + kk]);
                ah[2] = *(const uint32_t*)(&sA[0][r * SA_STRIDE + kk + 8]);
                ah[3] = *(const uint32_t*)(&sA[0][(r + 8) * SA_STRIDE + kk + 8]);
                al[0] = *(const uint32_t*)(&sA[1][r * SA_STRIDE + kk]);
                al[1] = *(const uint32_t*)(&sA[1][(r + 8) * SA_STRIDE + kk]);
                al[2] = *(const uint32_t*)(&sA[1][r * SA_STRIDE + kk + 8]);
                al[3] = *(const uint32_t*)(&sA[1][(r + 8) * SA_STRIDE + kk + 8]);
#pragma unroll
                for (int n = 0; n < 5; n++) {
                    mma16816(acc[m][n], ah, bf[n][0]);   // hi*hi
                    mma16816(acc[m][n], ah, bf[n][1]);   // hi*lo
                    mma16816(acc[m][n], al, bf[n][0]);   // lo*hi
                }
            }
        }
        __syncthreads();
    }
    // epilogue: write a
#pragma unroll
    for (int m = 0; m < 2; m++)
#pragma unroll
        for (int n = 0; n < 5; n++) {
            int r = row0 + mrow + m * 16 + (lane >> 2);
            int c = ncol + n * 8 + (lane & 3) * 2;
            g_a[(size_t)r * KG_ + c]           = acc[m][n][0];
            g_a[(size_t)r * KG_ + c + 1]       = acc[m][n][1];
            g_a[(size_t)(r + 8) * KG_ + c]     = acc[m][n][2];
            g_a[(size_t)(r + 8) * KG_ + c + 1] = acc[m][n][3];
        }
}

// ---------------- K2: per-column sum / sumsq over 131072 rows ----------------
__global__ void k2_stats() {
    __shared__ float ps[3][KG_], pq[3][KG_];
    int tid = threadIdx.x;
    if (tid < 240) {
        int c = tid % KG_, rp = tid / KG_;
        size_t base = (size_t)blockIdx.x * 1024;
        float s = 0.0f, q = 0.0f;
        for (int r = rp; r < 1024; r += 3) {
            float v = g_a[(base + r) * KG_ + c];
            s += v; q += v * v;
        }
        ps[rp][c] = s; pq[rp][c] = q;
    }
    __syncthreads();
    if (tid < KG_) {
        atomicAdd(&g_colsum[tid],   ps[0][tid] + ps[1][tid] + ps[2][tid]);
        atomicAdd(&g_colsumsq[tid], pq[0][tid] + pq[1][tid] + pq[2][tid]);
    }
}

// ---------------- K3: BN + softmax -> assignment^T (hi/lo) + a_sum ----------
__global__ __launch_bounds__(256)
void k3_softmax(const float* __restrict__ bn_w, const float* __restrict__ bn_b) {
    __shared__ float srow[128 * 81];
    __shared__ float s_scale[KG_], s_shift[KG_];
    __shared__ float s_part[4][K_];
    const int tid = threadIdx.x;
    const float inv_cnt = 1.0f / (float)ROWS_TOTAL;

    if (tid < KG_) {
        float mean = g_colsum[tid] * inv_cnt;
        float var  = g_colsumsq[tid] * inv_cnt - mean * mean;
        float sc   = rsqrtf(var + 1e-5f) * bn_w[tid];
        s_scale[tid] = sc;
        s_shift[tid] = bn_b[tid] - mean * sc;
    }
    __syncthreads();

    const int row0 = blockIdx.x * 128;
    const float* ab = g_a + (size_t)row0 * KG_;
    for (int i = tid; i < 128 * KG_; i += 256) {
        int r = i / KG_, c = i % KG_;
        srow[r * 81 + c] = ab[i] * s_scale[c] + s_shift[c];
    }
    __syncthreads();

    if (tid < 128) {
        float* row = srow + tid * 81;
        float mx = row[0];
#pragma unroll
        for (int j = 1; j < KG_; j++) mx = fmaxf(mx, row[j]);
        float s = 0.0f;
#pragma unroll
        for (int j = 0; j < KG_; j++) { float e = __expf(row[j] - mx); row[j] = e; s += e; }
        float inv = 1.0f / s;
#pragma unroll
        for (int j = 0; j < K_; j++) row[j] *= inv;
    }
    __syncthreads();

    const int b  = row0 >> 11;          // /2048
    const int n0 = row0 & (N_ - 1);
    // store transposed assignment, packed bf16x2 (coalesced 4B stores)
    for (int i = tid; i < K_ * 64; i += 256) {
        int k = i >> 6, rp = (i & 63) * 2;
        float p0 = srow[rp * 81 + k];
        float p1 = srow[(rp + 1) * 81 + k];
        __nv_bfloat16 h0, l0, h1, l1;
        split_bf16(p0, h0, l0);
        split_bf16(p1, h1, l1);
        size_t o = ((size_t)(b * K_ + k)) * N_ + n0 + rp;
        *(__nv_bfloat162*)(g_at_hi + o) = __nv_bfloat162(h0, h1);
        *(__nv_bfloat162*)(g_at_lo + o) = __nv_bfloat162(l0, l1);
    }
    // a_sum partials
    {
        int c = tid & 63, part = tid >> 6;
        float s = 0.0f;
        for (int r = part * 32; r < part * 32 + 32; r++) s += srow[r * 81 + c];
        s_part[part][c] = s;
    }
    __syncthreads();
    if (tid < K_) {
        float s = s_part[0][tid] + s_part[1][tid] + s_part[2][tid] + s_part[3][tid];
        atomicAdd(&g_asum[b * K_ + tid], s);
    }
}

// ---------------- K4: vlad[b,k,d] = sum_n assign^T[k,n]*x[n,d] - asum*c2 ----
// M=k(64)=2 Mwarps, Ntile=d(64)=4 Nwarps; n-chunk 32. grid (8 dtiles, 64 b).
#define S4_STRIDE 40
__global__ __launch_bounds__(256, 2)
void k4_gemm2(const float* __restrict__ x, const float* __restrict__ clusters2) {
    __shared__ __nv_bfloat16 sA[2][K_ * S4_STRIDE];   // assign^T chunk [k][n]
    __shared__ __nv_bfloat16 sB[2][64 * S4_STRIDE];   // x chunk transposed [d][n]
    const int tid = threadIdx.x, warp = tid >> 5, lane = tid & 31;
    const int d0 = blockIdx.x * 64;
    const int b  = blockIdx.y;
    const float* xb = x + (size_t)b * N_ * D_;
    const uint32_t* athi = (const uint32_t*)(g_at_hi + (size_t)b * K_ * N_);
    const uint32_t* atlo = (const uint32_t*)(g_at_lo + (size_t)b * K_ * N_);

    const int mbase = (warp & 1) * 32;
    const int nbase = (warp >> 1) * 16;

    float acc[2][2][4];
#pragma unroll
    for (int m = 0; m < 2; m++)
#pragma unroll
        for (int n = 0; n < 2; n++)
#pragma unroll
            for (int j = 0; j < 4; j++) acc[m][n][j] = 0.0f;

    for (int n0 = 0; n0 < N_; n0 += 32) {
        // assignment chunk: 64 k-rows x 16 u32 (32 bf16)
#pragma unroll
        for (int p = 0; p < 4; p++) {
            int i  = p * 256 + tid;                // < 1024
            int k  = i >> 4, np = i & 15;
            uint32_t hv = athi[k * (N_ / 2) + (n0 >> 1) + np];
            uint32_t lv = atlo[k * (N_ / 2) + (n0 >> 1) + np];
            *(uint32_t*)(&sA[0][k * S4_STRIDE + np * 2]) = hv;
            *(uint32_t*)(&sA[1][k * S4_STRIDE + np * 2]) = lv;
        }
        // x chunk 32n x 64d fp32, split + transpose into [d][n]
#pragma unroll
        for (int p = 0; p < 8; p++) {
            int i  = p * 256 + tid;                // < 2048
            int nn = i >> 6, dd = i & 63;
            float v = xb[(size_t)(n0 + nn) * D_ + d0 + dd];
            __nv_bfloat16 h, l;
            split_bf16(v, h, l);
            sB[0][dd * S4_STRIDE + nn] = h;
            sB[1][dd * S4_STRIDE + nn] = l;
        }
        __syncthreads();

#pragma unroll
        for (int ks = 0; ks < 2; ks++) {
            const int kb = ks * 16;
            const int kk = kb + (lane & 3) * 2;
            uint32_t bf[2][2][2];
#pragma unroll
            for (int n = 0; n < 2; n++) {
                int dc = nbase + n * 8 + (lane >> 2);
#pragma unroll
                for (int s = 0; s < 2; s++) {
                    bf[n][s][0] = *(const uint32_t*)(&sB[s][dc * S4_STRIDE + kk]);
                    bf[n][s][1] = *(const uint32_t*)(&sB[s][dc * S4_STRIDE + kk + 8]);
                }
            }
#pragma unroll
            for (int m = 0; m < 2; m++) {
                int r = mbase + m * 16 + (lane >> 2);
                uint32_t ah[4], al[4];
                ah[0] = *(const uint32_t*)(&sA[0][r * S4_STRIDE + kk]);
                ah[1] = *(const uint32_t*)(&sA[0][(r + 8) * S4_STRIDE + kk]);
                ah[2] = *(const uint32_t*)(&sA[0][r * S4_STRIDE + kk + 8]);
                ah[3] = *(const uint32_t*)(&sA[0][(r + 8) * S4_STRIDE + kk + 8]);
                al[0] = *(const uint32_t*)(&sA[1][r * S4_STRIDE + kk]);
                al[1] = *(const uint32_t*)(&sA[1][(r + 8) * S4_STRIDE + kk]);
                al[2] = *(const uint32_t*)(&sA[1][r * S4_STRIDE + kk + 8]);
                al[3] = *(const uint32_t*)(&sA[1][(r + 8) * S4_STRIDE + kk + 8]);
#pragma unroll
                for (int n = 0; n < 2; n++) {
                    mma16816(acc[m][n], ah, bf[n][0]);
                    mma16816(acc[m][n], ah, bf[n][1]);
                    mma16816(acc[m][n], al, bf[n][0]);
                }
            }
        }
        __syncthreads();
    }
    // epilogue: subtract a_sum*clusters2, write vlad_raw (B,K,D)
#pragma unroll
    for (int m = 0; m < 2; m++)
#pragma unroll
        for (int n = 0; n < 2; n++) {
            int kbase = mbase + m * 16 + (lane >> 2);
            int d = d0 + nbase + n * 8 + (lane & 3) * 2;
#pragma unroll
            for (int h = 0; h < 2; h++) {
                int kk = kbase + h * 8;
                float as = g_asum[b * K_ + kk];
                float v0 = acc[m][n][h * 2 + 0] - as * clusters2[(size_t)(d + 0) * K_ + kk];
                float v1 = acc[m][n][h * 2 + 1] - as * clusters2[(size_t)(d + 1) * K_ + kk];
                float* dst = g_vraw + ((size_t)(b * K_ + kk)) * D_ + d;
                dst[0] = v0; dst[1] = v1;
            }
        }
}

// ---------------- K5: intra-normalize over D, global normalize, transpose ---
__global__ __launch_bounds__(256)
void k5_norm(float* __restrict__ out) {
    __shared__ float tile[K_ * 129];
    __shared__ float s_scale[K_];
    __shared__ float s_n2[K_];
    const int tid = threadIdx.x, warp = tid >> 5, lane = tid & 31;
    const int b = blockIdx.x;
    const float* vb = g_vraw + (size_t)b * K_ * D_;

    for (int k = warp; k < K_; k += 8) {
        const float* row = vb + (size_t)k * D_;
        float s = 0.0f;
        for (int j = lane; j < D_; j += 32) { float v = row[j]; s += v * v; }
#pragma unroll
        for (int o = 16; o; o >>= 1) s += __shfl_xor_sync(0xffffffffu, s, o);
        if (lane == 0) s_n2[k] = s;
    }
    __syncthreads();
    if (tid < K_) {
        float n  = sqrtf(s_n2[tid]);
        float sc = 1.0f / fmaxf(n, 1e-12f);
        s_scale[tid] = sc;
        float vn = n * sc;
        s_n2[tid] = vn * vn;           // contribution to global norm (==1 normally)
    }
    __syncthreads();
    if (warp == 0) {
        float s = s_n2[lane] + s_n2[lane + 32];
#pragma unroll
        for (int o = 16; o; o >>= 1) s += __shfl_xor_sync(0xffffffffu, s, o);
        if (lane == 0) s_n2[0] = 1.0f / fmaxf(sqrtf(s), 1e-12f);
    }
    __syncthreads();
    const float g = s_n2[0];
    float* ob = out + (size_t)b * (D_ * K_);

    for (int dc = 0; dc < D_; dc += 128) {
        for (int i = tid; i < K_ * 128; i += 256) {
            int k = i >> 7, d = i & 127;
            tile[k * 129 + d] = vb[(size_t)k * D_ + dc + d] * s_scale[k] * g;
        }
        __syncthreads();
        for (int i = tid; i < K_ * 128; i += 256) {
            int d = i >> 6, k = i & 63;
            ob[(size_t)(dc + d) * K_ + k] = tile[k * 129 + d];
        }
        __syncthreads();
    }
}

// ---------------- launch ----------------------------------------------------
extern "C" void kernel_launch(void* const* d_in, const int* in_sizes, int n_in,
                              void* d_out, int out_size) {
    const float* x         = (const float*)d_in[0];   // (64, 2048, 512)
    const float* clusters  = (const float*)d_in[1];   // (512, 80)
    const float* clusters2 = (const float*)d_in[2];   // (1, 512, 64)
    const float* bn_w      = (const float*)d_in[3];   // (80,)
    const float* bn_b      = (const float*)d_in[4];   // (80,)
    float* out = (float*)d_out;                       // (64, 32768)

    k0_zero<<<16, 256>>>();
    k1_gemm1<<<ROWS_TOTAL / 128, 256>>>(x, clusters);
    k2_stats<<<ROWS_TOTAL / 1024, 256>>>();
    k3_softmax<<<ROWS_TOTAL / 128, 256>>>(bn_w, bn_b);
    k4_gemm2<<<dim3(D_ / 64, B_), 256>>>(x, clusters2);
    k5_norm<<<B_, 256>>>(out);
}